// round 3
// baseline (speedup 1.0000x reference)
#include <cuda_runtime.h>
#include <math.h>

#define BB 8
#define SS 256
#define HH 100
#define PP 20
#define NP 21                 // 20 weighted perspectives + 1 unweighted (cos)
#define EPSF 1e-8f
#define NTOK (BB*SS)
#define OD 105
#define NEGINF -3.0e38f

// ---------------- scratch ----------------
__device__ float g_cp[NTOK*HH], g_ch[NTOK*HH];     // masked contexts [tok][h]
__device__ float g_cpT[BB*HH*SS], g_chT[BB*HH*SS]; // transposed [b][h][i]
__device__ float g_np[NTOK], g_nh[NTOK];
__device__ float g_wn[2][4][NTOK*PP];              // [side][full,maxpool,att,maxatt]
__device__ int   g_len[2][BB];
__device__ float g_last[2][BB*HH];
__device__ float g_cos[BB*SS*SS];
__device__ float g_rowsum[NTOK], g_colsum[NTOK];
__device__ float g_att_mean[2][NTOK*HH];
__device__ float g_att_max[2][NTOK*HH];
__device__ float g_psum[2][BB*NP*SS], g_pmax[2][BB*NP*SS];  // j-half partials

// ---------------- K0: per-token prep ----------------------------------------------
__global__ void k_prep(const float* __restrict__ ctx_p, const int* __restrict__ mask_p,
                       const float* __restrict__ ctx_h, const int* __restrict__ mask_h,
                       const float* __restrict__ w_full, const float* __restrict__ w_mp,
                       const float* __restrict__ w_att, const float* __restrict__ w_ma)
{
    __shared__ float vsq[8][HH];
    int wl = threadIdx.x >> 5;
    int lane = threadIdx.x & 31;
    int gw = blockIdx.x * 8 + wl;
    int side = gw / NTOK;
    int tok = gw % NTOK;
    const float* ctx = side ? ctx_h : ctx_p;
    const int* mask = side ? mask_h : mask_p;
    float* dst = side ? g_ch : g_cp;
    float m = (float)mask[tok];
    float q = 0.f;
    for (int h = lane; h < HH; h += 32) {
        float v = ctx[tok*HH + h] * m;
        dst[tok*HH + h] = v;
        float v2 = v * v;
        vsq[wl][h] = v2;
        q += v2;
    }
    #pragma unroll
    for (int o = 16; o; o >>= 1) q += __shfl_xor_sync(0xffffffffu, q, o);
    if (lane == 0) (side ? g_nh : g_np)[tok] = sqrtf(q);
    __syncwarp();
    const float* ws[4] = {w_full, w_mp, w_att, w_ma};
    for (int c = lane; c < 4*PP; c += 32) {
        int w = c / PP, p = c % PP;
        const float* wr = ws[w] + p*HH;
        float s = 0.f;
        #pragma unroll 4
        for (int h = 0; h < HH; h++) { float ww = wr[h]; s += ww*ww*vsq[wl][h]; }
        g_wn[side][w][tok*PP + p] = sqrtf(s);
    }
}

// ---------------- K0b: lengths + last token ---------------------------------------
__global__ void k_len_last(const int* __restrict__ mask_p, const int* __restrict__ mask_h)
{
    int w = threadIdx.x >> 5;
    int lane = threadIdx.x & 31;
    int side = w / BB, b = w % BB;
    const int* mask = side ? mask_h : mask_p;
    int s = 0;
    for (int j = lane; j < SS; j += 32) s += mask[b*SS + j];
    #pragma unroll
    for (int o = 16; o; o >>= 1) s += __shfl_xor_sync(0xffffffffu, s, o);
    if (lane == 0) g_len[side][b] = s;
    s = __shfl_sync(0xffffffffu, s, 0);
    int last = s > 0 ? s - 1 : 0;
    const float* src = (side ? g_ch : g_cp) + (b*SS + last)*HH;
    float* dst = g_last[side] + b*HH;
    for (int h = lane; h < 32*((HH+31)/32); h += 32) if (h < HH) dst[h] = src[h];
}

// ---------------- K0c: transpose --------------------------------------------------
__global__ void __launch_bounds__(256) k_trans()
{
    int i0 = blockIdx.x * 64, b = blockIdx.y, side = blockIdx.z;
    __shared__ float tile[64][101];
    int t = threadIdx.x;
    const float* src = (side ? g_ch : g_cp) + (b*SS + i0)*HH;
    for (int e = t; e < 64*HH; e += 256) tile[e/HH][e%HH] = src[e];
    __syncthreads();
    int i = t & 63, g = t >> 6;
    float* dstT = (side ? g_chT : g_cpT) + b*HH*SS + i0 + i;
    for (int h = g; h < HH; h += 4) dstT[h*SS] = tile[i][h];
}

// ---------------- K1: unified GEMM + fused reductions -----------------------------
// grid (jhalf=2, p=21, b=8). Block: all 256 i x 128 j for one (b,p,jhalf).
// p<20: maxpool perspective (A scaled by w_mp[p]^2). p==20: plain cos.
// Epilogue: over-i (h-side) reduction completes in-block -> direct out / colsum;
// over-j (p-side) partial per half -> g_psum/g_pmax, combined in k_comb.
__global__ void __launch_bounds__(256, 2) k_pw_all(const float* __restrict__ w_mp,
                                                   float* __restrict__ out)
{
    int jh = blockIdx.x, p = blockIdx.y, b = blockIdx.z;
    int j0 = jh * 128;
    __shared__ float As2[20][256];   // duplicated pairs (a,a)
    __shared__ float Bs[20][128];
    __shared__ float wsq[HH];
    __shared__ float n1s[SS], n2s[128];
    __shared__ float hsS[8][128], hmS[8][128];

    int t = threadIdx.x, tx = t & 31, ty = t >> 5;
    int lh = g_len[1][b], lp = g_len[0][b];

    // norms + weights to smem
    if (t < HH) {
        if (p < PP) { float w = w_mp[p*HH + t]; wsq[t] = w*w; }
        else wsq[t] = 1.0f;
    }
    {
        int gi = b*SS + t;
        n1s[t] = (p < PP) ? g_wn[0][1][gi*PP + p] : fmaxf(g_np[gi], EPSF);
        if (t < 128) {
            int gj = b*SS + j0 + t;
            n2s[t] = (p < PP) ? g_wn[1][1][gj*PP + p] : fmaxf(g_nh[gj], EPSF);
        }
    }

    const float* gA = g_cpT + b*HH*SS;
    const float* gB = g_chT + b*HH*SS;

    // per-thread h-side running accumulators for j = j0 + {2tx,2tx+1,64+2tx,65+2tx}
    float hsum[4] = {0.f, 0.f, 0.f, 0.f};
    float hmax[4] = {NEGINF, NEGINF, NEGINF, NEGINF};

    for (int ic = 0; ic < 2; ic++) {
        int ibase = ic * 128;
        unsigned long long acc[16][2];
        #pragma unroll
        for (int r = 0; r < 16; r++) { acc[r][0] = 0ull; acc[r][1] = 0ull; }

        for (int k0 = 0; k0 < HH; k0 += 20) {
            __syncthreads();
            #pragma unroll
            for (int q = 0; q < 10; q++) {
                int e = t + 256*q;             // 2560 elems
                int kc = e >> 7, ii = e & 127;
                float v = wsq[k0 + kc] * gA[(k0 + kc)*SS + ibase + ii];
                float2 d; d.x = v; d.y = v;
                *(float2*)&As2[kc][ii*2] = d;
                Bs[kc][ii] = gB[(k0 + kc)*SS + j0 + ii];
            }
            __syncthreads();
            #pragma unroll
            for (int kc = 0; kc < 20; kc++) {
                unsigned long long b0 = *(const unsigned long long*)&Bs[kc][2*tx];
                unsigned long long b1 = *(const unsigned long long*)&Bs[kc][64 + 2*tx];
                #pragma unroll
                for (int r = 0; r < 16; r++) {
                    unsigned long long a2 =
                        *(const unsigned long long*)&As2[kc][(ty*16 + r)*2];
                    asm("fma.rn.f32x2 %0, %1, %2, %0;" : "+l"(acc[r][0]) : "l"(a2), "l"(b0));
                    asm("fma.rn.f32x2 %0, %1, %2, %0;" : "+l"(acc[r][1]) : "l"(a2), "l"(b1));
                }
            }
        }

        // epilogue for this i-chunk
        #pragma unroll
        for (int r = 0; r < 16; r++) {
            int i = ibase + ty*16 + r;
            int gi = b*SS + i;
            float n1 = n1s[i];
            unsigned lo0, hi0, lo1, hi1;
            asm("mov.b64 {%0, %1}, %2;" : "=r"(lo0), "=r"(hi0) : "l"(acc[r][0]));
            asm("mov.b64 {%0, %1}, %2;" : "=r"(lo1), "=r"(hi1) : "l"(acc[r][1]));
            int ja = 2*tx, jb = 64 + 2*tx;      // j within half
            float v0 = __uint_as_float(lo0) / fmaxf(n1*n2s[ja],   EPSF);
            float v1 = __uint_as_float(hi0) / fmaxf(n1*n2s[ja+1], EPSF);
            float v2 = __uint_as_float(lo1) / fmaxf(n1*n2s[jb],   EPSF);
            float v3 = __uint_as_float(hi1) / fmaxf(n1*n2s[jb+1], EPSF);
            if (p == PP) {
                float2 s0; s0.x = v0; s0.y = v1;
                float2 s1; s1.x = v2; s1.y = v3;
                *(float2*)&g_cos[(size_t)gi*SS + j0 + ja] = s0;
                *(float2*)&g_cos[(size_t)gi*SS + j0 + jb] = s1;
            }
            // p-side: reduce over this block's 128 j
            float sm = v0 + v1 + v2 + v3;
            float mx = NEGINF;
            if (j0 + ja     < lh) mx = fmaxf(mx, v0);
            if (j0 + ja + 1 < lh) mx = fmaxf(mx, v1);
            if (j0 + jb     < lh) mx = fmaxf(mx, v2);
            if (j0 + jb + 1 < lh) mx = fmaxf(mx, v3);
            #pragma unroll
            for (int o = 16; o; o >>= 1) {
                sm += __shfl_xor_sync(0xffffffffu, sm, o);
                mx = fmaxf(mx, __shfl_xor_sync(0xffffffffu, mx, o));
            }
            if (tx == 0) {
                int idx = (b*NP + p)*SS + i;
                g_psum[jh][idx] = sm;
                g_pmax[jh][idx] = mx;
            }
            // h-side accumulate
            hsum[0] += v0; hsum[1] += v1; hsum[2] += v2; hsum[3] += v3;
            if (i < lp) {
                hmax[0] = fmaxf(hmax[0], v0);
                hmax[1] = fmaxf(hmax[1], v1);
                hmax[2] = fmaxf(hmax[2], v2);
                hmax[3] = fmaxf(hmax[3], v3);
            }
        }
    }

    // h-side cross-ty reduce: sums first, then maxes (reuse smem)
    __syncthreads();
    hsS[ty][2*tx] = hsum[0];  hsS[ty][2*tx+1] = hsum[1];
    hsS[ty][64+2*tx] = hsum[2]; hsS[ty][65+2*tx] = hsum[3];
    hmS[ty][2*tx] = hmax[0];  hmS[ty][2*tx+1] = hmax[1];
    hmS[ty][64+2*tx] = hmax[2]; hmS[ty][65+2*tx] = hmax[3];
    __syncthreads();
    if (t < 128) {
        int j = t;
        float s = 0.f, m = NEGINF;
        #pragma unroll
        for (int y = 0; y < 8; y++) { s += hsS[y][j]; m = fmaxf(m, hmS[y][j]); }
        int gj = b*SS + j0 + j;
        if (p < PP) {
            float* o = out + (size_t)(NTOK + gj)*OD;
            o[23 + p] = m;
            o[43 + p] = s / (float)lp;
        } else {
            g_colsum[gj] = s;
            float* o = out + (size_t)(NTOK + gj)*OD;
            o[0] = m;
            o[1] = s / (float)lp;
        }
    }
}

// ---------------- K1b: combine p-side halves --------------------------------------
__global__ void k_comb(float* __restrict__ out)
{
    int bp = blockIdx.x;             // 0..167
    int b = bp / NP, p = bp % NP;
    int i = threadIdx.x;
    int idx = bp*SS + i;
    float sm = g_psum[0][idx] + g_psum[1][idx];
    float mx = fmaxf(g_pmax[0][idx], g_pmax[1][idx]);
    int lh = g_len[1][b];
    float* o = out + (size_t)(b*SS + i)*OD;
    if (p < PP) {
        o[23 + p] = mx;
        o[43 + p] = sm / (float)lh;
    } else {
        g_rowsum[b*SS + i] = sm;
        o[0] = mx;
        o[1] = sm / (float)lh;
    }
}

// ---------------- K3: attentive mean + max ----------------------------------------
__global__ void k_att_h()
{
    int b = blockIdx.x, it = blockIdx.y;
    __shared__ float cs[8][SS];
    int t = threadIdx.x;   // 128
    for (int e = t; e < 8*SS; e += 128) {
        int il = e >> 8, j = e & 255;
        cs[il][j] = g_cos[(b*SS + it*8 + il)*SS + j];
    }
    __syncthreads();
    int lh = g_len[1][b];
    int h = t;
    if (h < HH) {
        float sm[8], mx[8];
        #pragma unroll
        for (int il = 0; il < 8; il++) { sm[il] = 0.f; mx[il] = NEGINF; }
        for (int j = 0; j < lh; j++) {
            float c = __ldg(&g_ch[(b*SS + j)*HH + h]);
            #pragma unroll
            for (int il = 0; il < 8; il++) {
                float f = cs[il][j] * c;
                sm[il] += f;
                mx[il] = fmaxf(mx[il], f);
            }
        }
        #pragma unroll
        for (int il = 0; il < 8; il++) {
            int tok = b*SS + it*8 + il;
            g_att_mean[0][tok*HH + h] = sm[il] / fmaxf(g_rowsum[tok], EPSF);
            g_att_max[0][tok*HH + h] = mx[il];
        }
    }
}

__global__ void k_att_p()
{
    int b = blockIdx.x, jt = blockIdx.y;
    __shared__ float cs[8][SS + 1];
    int t = threadIdx.x;   // 128
    for (int e = t; e < 8*SS; e += 128) {
        int i = e >> 3, jl = e & 7;
        cs[jl][i] = g_cos[(b*SS + i)*SS + jt*8 + jl];
    }
    __syncthreads();
    int lp = g_len[0][b];
    int h = t;
    if (h < HH) {
        float sm[8], mx[8];
        #pragma unroll
        for (int jl = 0; jl < 8; jl++) { sm[jl] = 0.f; mx[jl] = NEGINF; }
        for (int i = 0; i < lp; i++) {
            float c = __ldg(&g_cp[(b*SS + i)*HH + h]);
            #pragma unroll
            for (int jl = 0; jl < 8; jl++) {
                float f = cs[jl][i] * c;
                sm[jl] += f;
                mx[jl] = fmaxf(mx[jl], f);
            }
        }
        #pragma unroll
        for (int jl = 0; jl < 8; jl++) {
            int tok = b*SS + jt*8 + jl;
            g_att_mean[1][tok*HH + h] = sm[jl] / fmaxf(g_colsum[tok], EPSF);
            g_att_max[1][tok*HH + h] = mx[jl];
        }
    }
}

// ---------------- K4: multi-perspective match -------------------------------------
__global__ void k_match(const float* __restrict__ w_full, const float* __restrict__ w_att,
                        const float* __restrict__ w_ma, float* __restrict__ out)
{
    int which = blockIdx.y;
    int side = blockIdx.z;
    int gw = blockIdx.x*8 + (threadIdx.x >> 5);
    int lane = threadIdx.x & 31;
    int b = gw / SS;

    const float* v1 = (side ? g_ch : g_cp) + gw*HH;
    const float* wn1;
    const float* v2;
    const float* w;
    int col;
    if (which == 0) {
        wn1 = g_wn[side][0]; v2 = g_last[side ^ 1] + b*HH; w = w_full; col = 2;
    } else if (which == 1) {
        wn1 = g_wn[side][2]; v2 = g_att_mean[side] + gw*HH; w = w_att; col = 63;
    } else {
        wn1 = g_wn[side][3]; v2 = g_att_max[side] + gw*HH; w = w_ma; col = 84;
    }
    float* o = out + ((size_t)side*NTOK + gw)*OD;

    float r1[4], r2[4];
    float d = 0.f, q1 = 0.f, q2 = 0.f;
    #pragma unroll
    for (int k = 0; k < 4; k++) {
        int h = k*32 + lane;
        float a = (h < HH) ? v1[h] : 0.f;
        float c = (h < HH) ? v2[h] : 0.f;
        r1[k] = a; r2[k] = c;
        d += a*c; q1 += a*a; q2 += c*c;
    }
    #pragma unroll
    for (int of = 16; of; of >>= 1) {
        d  += __shfl_xor_sync(0xffffffffu, d, of);
        q1 += __shfl_xor_sync(0xffffffffu, q1, of);
        q2 += __shfl_xor_sync(0xffffffffu, q2, of);
    }
    if (lane == 0)
        o[col] = d / (fmaxf(sqrtf(q1), EPSF) * fmaxf(sqrtf(q2), EPSF));

    for (int p = 0; p < PP; p++) {
        float s12 = 0.f, s22 = 0.f;
        #pragma unroll
        for (int k = 0; k < 4; k++) {
            int h = k*32 + lane;
            float ww = (h < HH) ? w[p*HH + h] : 0.f;
            float w2 = ww*ww;
            s12 += w2 * r1[k] * r2[k];
            s22 += w2 * r2[k] * r2[k];
        }
        #pragma unroll
        for (int of = 16; of; of >>= 1) {
            s12 += __shfl_xor_sync(0xffffffffu, s12, of);
            s22 += __shfl_xor_sync(0xffffffffu, s22, of);
        }
        if (lane == 0) {
            float n1 = wn1[gw*PP + p];
            o[col + 1 + p] = s12 / (fmaxf(n1, EPSF) * fmaxf(sqrtf(s22), EPSF));
        }
    }
}

// ---------------- launcher --------------------------------------------------------
extern "C" void kernel_launch(void* const* d_in, const int* in_sizes, int n_in,
                              void* d_out, int out_size)
{
    const float* ctx_p  = (const float*)d_in[0];
    const int*   mask_p = (const int*)  d_in[1];
    const float* ctx_h  = (const float*)d_in[2];
    const int*   mask_h = (const int*)  d_in[3];
    const float* w_full = (const float*)d_in[4];
    const float* w_mp   = (const float*)d_in[5];
    const float* w_att  = (const float*)d_in[6];
    const float* w_ma   = (const float*)d_in[7];
    float* out = (float*)d_out;

    k_prep<<<512, 256>>>(ctx_p, mask_p, ctx_h, mask_h, w_full, w_mp, w_att, w_ma);
    k_len_last<<<1, 512>>>(mask_p, mask_h);
    k_trans<<<dim3(4, BB, 2), 256>>>();
    k_pw_all<<<dim3(2, NP, BB), 256>>>(w_mp, out);
    k_comb<<<BB*NP, 256>>>(out);
    k_att_h<<<dim3(BB, 32), 128>>>();
    k_att_p<<<dim3(BB, 32), 128>>>();
    k_match<<<dim3(256, 3, 2), 256>>>(w_full, w_att, w_ma, out);
}

// round 4
// speedup vs baseline: 1.5937x; 1.5937x over previous
#include <cuda_runtime.h>
#include <math.h>

#define BB 8
#define SS 256
#define HH 100
#define PP 20
#define NP 21                 // 20 maxpool perspectives + 1 unweighted (cos)
#define EPSF 1e-8f
#define NTOK (BB*SS)
#define OD 105
#define NEGINF -3.0e38f
typedef unsigned long long ull;

// ---------------- scratch ----------------
__device__ float g_cp[NTOK*HH], g_ch[NTOK*HH];     // masked contexts [tok][h]
__device__ float g_cpT[BB*HH*SS], g_chT[BB*HH*SS]; // transposed [b][h][i]
__device__ float g_np[NTOK], g_nh[NTOK];
__device__ float g_wn[2][4][NTOK*PP];              // [side][full,maxpool,att,maxatt]
__device__ int   g_len[2][BB];
__device__ float g_last[2][BB*HH];
__device__ float g_cos[BB*SS*SS];
__device__ float g_rowsum[NTOK], g_colsum[NTOK];
__device__ float g_att_mean[2][NTOK*HH];
__device__ float g_att_max[2][NTOK*HH];
__device__ float g_psum[2][BB*NP*SS], g_pmax[2][BB*NP*SS];  // over-j partials, [jh]
__device__ float g_hsum[2][BB*NP*SS], g_hmax[2][BB*NP*SS];  // over-i partials, [ih]

// ---------------- K0: prep (mask, norms, weighted norms) + transpose, fused ------
__global__ void __launch_bounds__(256) k_prep(
    const float* __restrict__ ctx_p, const int* __restrict__ mask_p,
    const float* __restrict__ ctx_h, const int* __restrict__ mask_h,
    const float* __restrict__ w_full, const float* __restrict__ w_mp,
    const float* __restrict__ w_att, const float* __restrict__ w_ma)
{
    __shared__ float tile[32][101];
    int c0 = blockIdx.x * 32, b = blockIdx.y, side = blockIdx.z;
    const float* ctx = side ? ctx_h : ctx_p;
    const int* mask = side ? mask_h : mask_p;
    float* rowdst = side ? g_ch : g_cp;
    float* Tdst = (side ? g_chT : g_cpT) + b*HH*SS;
    int t = threadIdx.x;
    int base = b*SS + c0;

    for (int e = t; e < 32*HH; e += 256) {
        int i = e / HH, h = e - i*HH;
        float v = ctx[(base + i)*HH + h] * (float)mask[base + i];
        tile[i][h] = v;
        rowdst[(base + i)*HH + h] = v;
    }
    __syncthreads();

    // unweighted norms: warp wl handles tokens wl*4..wl*4+3
    int lane = t & 31, wl = t >> 5;
    for (int k = 0; k < 4; k++) {
        int i = wl*4 + k;
        float q = 0.f;
        for (int h = lane; h < HH; h += 32) { float v = tile[i][h]; q += v*v; }
        #pragma unroll
        for (int o = 16; o; o >>= 1) q += __shfl_xor_sync(0xffffffffu, q, o);
        if (lane == 0) (side ? g_nh : g_np)[base + i] = sqrtf(q);
    }

    // weighted norms: 80 (w,p) x 32 tokens = 2560 tasks
    const float* ws[4] = {w_full, w_mp, w_att, w_ma};
    for (int it = 0; it < 10; it++) {
        int task = t + 256*it;
        int wp = task >> 5, i = task & 31;
        int w = wp / PP, p = wp - w*PP;
        const float* wr = ws[w] + p*HH;
        float s = 0.f;
        #pragma unroll 4
        for (int h = 0; h < HH; h++) {
            float ww = wr[h]; float v = tile[i][h];
            s += ww*ww*v*v;
        }
        g_wn[side][w][(base + i)*PP + p] = sqrtf(s);
    }

    // transposed writes
    int i = t & 31, hb = t >> 5;
    for (int h = hb; h < HH; h += 8) Tdst[h*SS + c0 + i] = tile[i][h];
}

// ---------------- K0b: lengths + last token ---------------------------------------
__global__ void k_len_last(const int* __restrict__ mask_p, const int* __restrict__ mask_h)
{
    int w = threadIdx.x >> 5;
    int lane = threadIdx.x & 31;
    int side = w / BB, b = w % BB;
    const int* mask = side ? mask_h : mask_p;
    int s = 0;
    for (int j = lane; j < SS; j += 32) s += mask[b*SS + j];
    #pragma unroll
    for (int o = 16; o; o >>= 1) s += __shfl_xor_sync(0xffffffffu, s, o);
    if (lane == 0) g_len[side][b] = s;
    s = __shfl_sync(0xffffffffu, s, 0);
    int last = s > 0 ? s - 1 : 0;
    const float* src = (side ? g_ch : g_cp) + (b*SS + last)*HH;
    float* dst = g_last[side] + b*HH;
    for (int h = lane; h < HH; h += 32) dst[h] = src[h];
}

// ---------------- K1: unified GEMM + fused bidirectional reductions ---------------
// grid (4 = ih*2+jh, p=21, b=8). Block: 128 i x 128 j. Thread: 8x8 via f32x2.
__global__ void __launch_bounds__(256, 2) k_pw_all(const float* __restrict__ w_mp,
                                                   float* __restrict__ out)
{
    __shared__ float smem_buf[20*256 + 20*128];   // As2 | Bs ; reused for h-side stage
    __shared__ float n1s[128], n2s[128], wsq[128];
    float (*As2)[256] = (float(*)[256])smem_buf;          // duplicated pairs (a,a)
    float (*Bs)[128] = (float(*)[128])(smem_buf + 20*256);

    int ih = blockIdx.x >> 1, jh = blockIdx.x & 1;
    int p = blockIdx.y, b = blockIdx.z;
    int t = threadIdx.x, tx = t & 15, ty = t >> 4;

    if (t < 128) {
        int gi = b*SS + ih*128 + t;
        float n1 = (p < PP) ? g_wn[0][1][gi*PP + p] : g_np[gi];
        n1s[t] = 1.0f / fmaxf(n1, (p < PP) ? 1e-4f : EPSF);
        int gj = b*SS + jh*128 + t;
        float n2 = (p < PP) ? g_wn[1][1][gj*PP + p] : g_nh[gj];
        n2s[t] = 1.0f / fmaxf(n2, (p < PP) ? 1e-4f : EPSF);
    }
    if (t < HH) {
        if (p < PP) { float w = w_mp[p*HH + t]; wsq[t] = w*w; }
        else wsq[t] = 1.0f;
    }

    const float* gA = g_cpT + b*HH*SS + ih*128;
    const float* gB = g_chT + b*HH*SS + jh*128;

    ull acc[8][4];
    #pragma unroll
    for (int r = 0; r < 8; r++)
        #pragma unroll
        for (int c = 0; c < 4; c++) acc[r][c] = 0ull;

    float aReg[10], bReg[10];
    // prefetch chunk 0
    #pragma unroll
    for (int q = 0; q < 10; q++) {
        int e = t + 256*q;
        int kc = e >> 7, ii = e & 127;
        aReg[q] = gA[kc*SS + ii];
        bReg[q] = gB[kc*SS + ii];
    }

    for (int ch = 0; ch < 5; ch++) {
        __syncthreads();
        int k0 = ch*20;
        #pragma unroll
        for (int q = 0; q < 10; q++) {
            int e = t + 256*q;
            int kc = e >> 7, ii = e & 127;
            float av = wsq[k0 + kc] * aReg[q];
            float2 d; d.x = av; d.y = av;
            *(float2*)&As2[kc][ii*2] = d;
            Bs[kc][ii] = bReg[q];
        }
        __syncthreads();
        if (ch < 4) {
            int k0n = (ch + 1)*20;
            #pragma unroll
            for (int q = 0; q < 10; q++) {
                int e = t + 256*q;
                int kc = e >> 7, ii = e & 127;
                aReg[q] = gA[(k0n + kc)*SS + ii];
                bReg[q] = gB[(k0n + kc)*SS + ii];
            }
        }
        #pragma unroll
        for (int kc = 0; kc < 20; kc++) {
            const ulonglong2* bp = (const ulonglong2*)&Bs[kc][tx*8];
            ulonglong2 bv0 = bp[0], bv1 = bp[1];
            ull b2[4] = {bv0.x, bv0.y, bv1.x, bv1.y};
            const ulonglong2* ap = (const ulonglong2*)&As2[kc][ty*16];
            ulonglong2 av0 = ap[0], av1 = ap[1], av2 = ap[2], av3 = ap[3];
            ull a2[8] = {av0.x, av0.y, av1.x, av1.y, av2.x, av2.y, av3.x, av3.y};
            #pragma unroll
            for (int r = 0; r < 8; r++)
                #pragma unroll
                for (int c = 0; c < 4; c++)
                    asm("fma.rn.f32x2 %0, %1, %2, %0;"
                        : "+l"(acc[r][c]) : "l"(a2[r]), "l"(b2[c]));
        }
    }

    // ---------------- epilogue ----------------
    int lh = g_len[1][b], lp = g_len[0][b];
    float csum[8], cmax[8];
    #pragma unroll
    for (int k = 0; k < 8; k++) { csum[k] = 0.f; cmax[k] = NEGINF; }

    #pragma unroll
    for (int r = 0; r < 8; r++) {
        int iloc = ty*8 + r;
        int gi = b*SS + ih*128 + iloc;
        float n1i = n1s[iloc];
        float v[8];
        #pragma unroll
        for (int c = 0; c < 4; c++) {
            unsigned lo, hi;
            asm("mov.b64 {%0, %1}, %2;" : "=r"(lo), "=r"(hi) : "l"(acc[r][c]));
            v[2*c]   = __uint_as_float(lo) * n1i * n2s[tx*8 + 2*c];
            v[2*c+1] = __uint_as_float(hi) * n1i * n2s[tx*8 + 2*c + 1];
        }
        if (p == PP) {
            float4 s0 = make_float4(v[0], v[1], v[2], v[3]);
            float4 s1 = make_float4(v[4], v[5], v[6], v[7]);
            float* dst = g_cos + (size_t)gi*SS + jh*128 + tx*8;
            *(float4*)dst = s0;
            *(float4*)(dst + 4) = s1;
        }
        // over-j partial for this row
        float sm = 0.f, mx = NEGINF;
        #pragma unroll
        for (int k = 0; k < 8; k++) {
            sm += v[k];
            if (jh*128 + tx*8 + k < lh) mx = fmaxf(mx, v[k]);
        }
        #pragma unroll
        for (int o = 8; o; o >>= 1) {
            sm += __shfl_xor_sync(0xffffffffu, sm, o);
            mx = fmaxf(mx, __shfl_xor_sync(0xffffffffu, mx, o));
        }
        if (tx == 0) {
            int idx = (b*NP + p)*SS + ih*128 + iloc;
            g_psum[jh][idx] = sm;
            g_pmax[jh][idx] = mx;
        }
        // over-i accumulate
        bool valid = (ih*128 + iloc) < lp;
        #pragma unroll
        for (int k = 0; k < 8; k++) {
            csum[k] += v[k];
            if (valid) cmax[k] = fmaxf(cmax[k], v[k]);
        }
    }

    // stage over-i partials: reuse smem_buf
    __syncthreads();
    float* hsP = smem_buf;               // [16][136]
    float* hmP = smem_buf + 16*136;
    #pragma unroll
    for (int k = 0; k < 8; k++) {
        hsP[ty*136 + tx*8 + k] = csum[k];
        hmP[ty*136 + tx*8 + k] = cmax[k];
    }
    __syncthreads();
    if (t < 128) {
        float s = 0.f, m = NEGINF;
        #pragma unroll
        for (int y = 0; y < 16; y++) {
            s += hsP[y*136 + t];
            m = fmaxf(m, hmP[y*136 + t]);
        }
        int idx = (b*NP + p)*SS + jh*128 + t;
        g_hsum[ih][idx] = s;
        g_hmax[ih][idx] = m;
    }
}

// ---------------- K1b: combine halves, both directions ----------------------------
__global__ void k_comb(float* __restrict__ out)
{
    int bp = blockIdx.x;             // 0..167
    int b = bp / NP, p = bp % NP;
    int t = threadIdx.x;             // token index within b (i or j)
    int idx = bp*SS + t;
    int lh = g_len[1][b], lp = g_len[0][b];
    // over-j (p-side, rows of side 0)
    float sm = g_psum[0][idx] + g_psum[1][idx];
    float mx = fmaxf(g_pmax[0][idx], g_pmax[1][idx]);
    float* op = out + (size_t)(b*SS + t)*OD;
    // over-i (h-side, rows of side 1)
    float hs = g_hsum[0][idx] + g_hsum[1][idx];
    float hm = fmaxf(g_hmax[0][idx], g_hmax[1][idx]);
    float* oh = out + (size_t)(NTOK + b*SS + t)*OD;
    if (p < PP) {
        op[23 + p] = mx;  op[43 + p] = sm / (float)lh;
        oh[23 + p] = hm;  oh[43 + p] = hs / (float)lp;
    } else {
        g_rowsum[b*SS + t] = sm;
        op[0] = mx;  op[1] = sm / (float)lh;
        g_colsum[b*SS + t] = hs;
        oh[0] = hm;  oh[1] = hs / (float)lp;
    }
}

// ---------------- K3: attentive mean + max (both sides, split reduce-dim) ---------
__global__ void __launch_bounds__(256) k_att()
{
    int b = blockIdx.x, tl = blockIdx.y, side = blockIdx.z;
    __shared__ float cs[8][257];
    __shared__ float red_s[2][8][104], red_m[2][8][104];
    int t = threadIdx.x;
    if (side == 0) {
        for (int e = t; e < 8*SS; e += 256) {
            int il = e >> 8, j = e & 255;
            cs[il][j] = g_cos[(b*SS + tl*8 + il)*SS + j];
        }
    } else {
        for (int e = t; e < 8*SS; e += 256) {
            int il = e & 7, i = e >> 3;
            cs[il][i] = g_cos[(b*SS + i)*SS + tl*8 + il];
        }
    }
    __syncthreads();
    int g = t >> 7, h = t & 127;
    int len = side ? g_len[0][b] : g_len[1][b];
    const float* vec = side ? g_cp : g_ch;
    int jbeg = g*128, jend = min(len, jbeg + 128);
    float sm[8], mx[8];
    #pragma unroll
    for (int il = 0; il < 8; il++) { sm[il] = 0.f; mx[il] = NEGINF; }
    if (h < HH) {
        for (int j = jbeg; j < jend; j++) {
            float c = __ldg(&vec[(b*SS + j)*HH + h]);
            #pragma unroll
            for (int il = 0; il < 8; il++) {
                float f = cs[il][j] * c;
                sm[il] += f;
                mx[il] = fmaxf(mx[il], f);
            }
        }
        #pragma unroll
        for (int il = 0; il < 8; il++) {
            red_s[g][il][h] = sm[il];
            red_m[g][il][h] = mx[il];
        }
    }
    __syncthreads();
    if (g == 0 && h < HH) {
        #pragma unroll
        for (int il = 0; il < 8; il++) {
            float s = red_s[0][il][h] + red_s[1][il][h];
            float m = fmaxf(red_m[0][il][h], red_m[1][il][h]);
            int tok = b*SS + tl*8 + il;
            float denom = side ? g_colsum[tok] : g_rowsum[tok];
            g_att_mean[side][tok*HH + h] = s / fmaxf(denom, EPSF);
            g_att_max[side][tok*HH + h] = m;
        }
    }
}

// ---------------- K4: multi-perspective match -------------------------------------
__global__ void k_match(const float* __restrict__ w_full, const float* __restrict__ w_att,
                        const float* __restrict__ w_ma, float* __restrict__ out)
{
    int which = blockIdx.y;
    int side = blockIdx.z;
    int gw = blockIdx.x*8 + (threadIdx.x >> 5);
    int lane = threadIdx.x & 31;
    int b = gw / SS;

    const float* v1 = (side ? g_ch : g_cp) + gw*HH;
    const float* wn1;
    const float* v2;
    const float* w;
    int col;
    if (which == 0) {
        wn1 = g_wn[side][0]; v2 = g_last[side ^ 1] + b*HH; w = w_full; col = 2;
    } else if (which == 1) {
        wn1 = g_wn[side][2]; v2 = g_att_mean[side] + gw*HH; w = w_att; col = 63;
    } else {
        wn1 = g_wn[side][3]; v2 = g_att_max[side] + gw*HH; w = w_ma; col = 84;
    }
    float* o = out + ((size_t)side*NTOK + gw)*OD;

    float r1[4], r2[4];
    float d = 0.f, q1 = 0.f, q2 = 0.f;
    #pragma unroll
    for (int k = 0; k < 4; k++) {
        int h = k*32 + lane;
        float a = (h < HH) ? v1[h] : 0.f;
        float c = (h < HH) ? v2[h] : 0.f;
        r1[k] = a; r2[k] = c;
        d += a*c; q1 += a*a; q2 += c*c;
    }
    #pragma unroll
    for (int of = 16; of; of >>= 1) {
        d  += __shfl_xor_sync(0xffffffffu, d, of);
        q1 += __shfl_xor_sync(0xffffffffu, q1, of);
        q2 += __shfl_xor_sync(0xffffffffu, q2, of);
    }
    if (lane == 0)
        o[col] = d / (fmaxf(sqrtf(q1), EPSF) * fmaxf(sqrtf(q2), EPSF));

    for (int p = 0; p < PP; p++) {
        float s12 = 0.f, s22 = 0.f;
        #pragma unroll
        for (int k = 0; k < 4; k++) {
            int h = k*32 + lane;
            float ww = (h < HH) ? w[p*HH + h] : 0.f;
            float w2 = ww*ww;
            s12 += w2 * r1[k] * r2[k];
            s22 += w2 * r2[k] * r2[k];
        }
        #pragma unroll
        for (int of = 16; of; of >>= 1) {
            s12 += __shfl_xor_sync(0xffffffffu, s12, of);
            s22 += __shfl_xor_sync(0xffffffffu, s22, of);
        }
        if (lane == 0) {
            float n1 = wn1[gw*PP + p];
            o[col + 1 + p] = s12 / (fmaxf(n1, EPSF) * fmaxf(sqrtf(s22), EPSF));
        }
    }
}

// ---------------- launcher --------------------------------------------------------
extern "C" void kernel_launch(void* const* d_in, const int* in_sizes, int n_in,
                              void* d_out, int out_size)
{
    const float* ctx_p  = (const float*)d_in[0];
    const int*   mask_p = (const int*)  d_in[1];
    const float* ctx_h  = (const float*)d_in[2];
    const int*   mask_h = (const int*)  d_in[3];
    const float* w_full = (const float*)d_in[4];
    const float* w_mp   = (const float*)d_in[5];
    const float* w_att  = (const float*)d_in[6];
    const float* w_ma   = (const float*)d_in[7];
    float* out = (float*)d_out;

    k_prep<<<dim3(8, BB, 2), 256>>>(ctx_p, mask_p, ctx_h, mask_h,
                                    w_full, w_mp, w_att, w_ma);
    k_len_last<<<1, 512>>>(mask_p, mask_h);
    k_pw_all<<<dim3(4, NP, BB), 256>>>(w_mp, out);
    k_comb<<<BB*NP, 256>>>(out);
    k_att<<<dim3(BB, 32, 2), 256>>>();
    k_match<<<dim3(256, 3, 2), 256>>>(w_full, w_att, w_ma, out);
}